// round 12
// baseline (speedup 1.0000x reference)
#include <cuda_runtime.h>
#include <cstdint>

// Problem constants
#define NN   32
#define CC   512
#define HWL  3136        // 56*56
#define GG   8
#define LL   64
#define MTOT 100352      // NN*HWL
#define EPSV 1e-4f
#define NPART 128        // 32 n-chunks * 4 k-chunks
#define RL   68          // smem row stride (floats) for [m][k]-style arrays
#define RLX  72          // smem row stride for apply's X [k][n]

// ---------------- scratch (device globals; no allocation allowed) -------------
__device__ float g_pcov[GG][NPART][LL * LL];  // partial Grams (octet-upper tiles)
__device__ float g_psum[GG][NPART][LL];       // partial channel sums
__device__ float g_mu[CC];
__device__ float g_cov[GG * LL * LL];
__device__ float g_subT[GG * LL * LL];        // whitening subspace, TRANSPOSED [g][k][i] = S[i][k]
__device__ float g_t[CC];                     // t[c] = sum_j S[c][j] * mu[g*64+j]

// ---------------- helpers ------------------------------------------------------
__device__ __forceinline__ void mma_tf32(float c[4],
                                         uint32_t a0, uint32_t a1, uint32_t a2, uint32_t a3,
                                         uint32_t b0, uint32_t b1) {
    asm volatile(
        "mma.sync.aligned.m16n8k8.row.col.f32.tf32.tf32.f32 "
        "{%0,%1,%2,%3}, {%4,%5,%6,%7}, {%8,%9}, {%0,%1,%2,%3};"
        : "+f"(c[0]), "+f"(c[1]), "+f"(c[2]), "+f"(c[3])
        : "r"(a0), "r"(a1), "r"(a2), "r"(a3), "r"(b0), "r"(b1));
}
__device__ __forceinline__ float hi_tf32(float x) {
    return __uint_as_float(__float_as_uint(x) & 0xFFFFE000u);
}
__device__ __forceinline__ uint32_t fbits(float x) { return __float_as_uint(x); }

// =============================================================================
// Cov MMA body: warp handles m-strips M1 (cols nt >= N1) and M2 (nt >= N2),
// sharing B fragments. 3xTF32. acc layout: [0 .. 8-N1) = strip M1,
// [8-N1 .. 8-N1 + 8-N2) = strip M2.
// =============================================================================
template<int M1, int N1, int M2, int N2>
__device__ __forceinline__ void cov_tile_mma(const float* __restrict__ Xhi,
                                             const float* __restrict__ Xlo,
                                             float (*acc)[4], int r, int c) {
    constexpr int T1 = 8 - N1;
    #pragma unroll
    for (int ks = 0; ks < 8; ++ks) {
        const int ka = 8 * ks + c;
        uint32_t a1h0 = fbits(Xhi[(M1 + r) * RL + ka]);
        uint32_t a1h1 = fbits(Xhi[(M1 + r + 8) * RL + ka]);
        uint32_t a1h2 = fbits(Xhi[(M1 + r) * RL + ka + 4]);
        uint32_t a1h3 = fbits(Xhi[(M1 + r + 8) * RL + ka + 4]);
        uint32_t a1l0 = fbits(Xlo[(M1 + r) * RL + ka]);
        uint32_t a1l1 = fbits(Xlo[(M1 + r + 8) * RL + ka]);
        uint32_t a1l2 = fbits(Xlo[(M1 + r) * RL + ka + 4]);
        uint32_t a1l3 = fbits(Xlo[(M1 + r + 8) * RL + ka + 4]);
        uint32_t a2h0 = fbits(Xhi[(M2 + r) * RL + ka]);
        uint32_t a2h1 = fbits(Xhi[(M2 + r + 8) * RL + ka]);
        uint32_t a2h2 = fbits(Xhi[(M2 + r) * RL + ka + 4]);
        uint32_t a2h3 = fbits(Xhi[(M2 + r + 8) * RL + ka + 4]);
        uint32_t a2l0 = fbits(Xlo[(M2 + r) * RL + ka]);
        uint32_t a2l1 = fbits(Xlo[(M2 + r + 8) * RL + ka]);
        uint32_t a2l2 = fbits(Xlo[(M2 + r) * RL + ka + 4]);
        uint32_t a2l3 = fbits(Xlo[(M2 + r + 8) * RL + ka + 4]);
        #pragma unroll
        for (int nt = N1; nt < 8; ++nt) {
            const int brow = nt * 8 + r;
            uint32_t bh0 = fbits(Xhi[brow * RL + ka]);
            uint32_t bh1 = fbits(Xhi[brow * RL + ka + 4]);
            uint32_t bl0 = fbits(Xlo[brow * RL + ka]);
            uint32_t bl1 = fbits(Xlo[brow * RL + ka + 4]);
            mma_tf32(acc[nt - N1], a1h0, a1h1, a1h2, a1h3, bh0, bh1);
            mma_tf32(acc[nt - N1], a1h0, a1h1, a1h2, a1h3, bl0, bl1);
            mma_tf32(acc[nt - N1], a1l0, a1l1, a1l2, a1l3, bh0, bh1);
            if (nt >= N2) {
                mma_tf32(acc[T1 + nt - N2], a2h0, a2h1, a2h2, a2h3, bh0, bh1);
                mma_tf32(acc[T1 + nt - N2], a2h0, a2h1, a2h2, a2h3, bl0, bl1);
                mma_tf32(acc[T1 + nt - N2], a2l0, a2l1, a2l2, a2l3, bh0, bh1);
            }
        }
    }
}

// =============================================================================
// Kernel 1: partial Gram (octet-level upper triangle) + channel sums, 3xTF32.
// grid (4 k-chunks, 32 n, 8 g), 64 threads (2 warps).
//   warp0: m-strips {0, 48}, col-tiles {nt>=0 (8), nt>=6 (2)}  -> 10 tiles
//   warp1: m-strips {16, 32}, col-tiles {nt>=2 (6), nt>=4 (4)} -> 10 tiles
// Balanced; B fragments shared across each warp's two strips.
// =============================================================================
__global__ __launch_bounds__(64) void k_cov_partial(const float* __restrict__ x) {
    const int q = blockIdx.x;           // k-chunk 0..3
    const int n = blockIdx.y;
    const int g = blockIdx.z;
    __shared__ __align__(16) float Xhi[64 * RL];
    __shared__ __align__(16) float Xlo[64 * RL];

    const int tid = threadIdx.x, wid = tid >> 5, lane = tid & 31;
    const int r = lane >> 2, c = lane & 3;
    const int lr = tid >> 4, lc = tid & 15;

    const int tiles = (q == 0) ? 13 : 12;
    const int k0    = (q == 0) ? 0 : (832 + (q - 1) * 768);
    const float* base = x + ((size_t)n * CC + (size_t)g * LL) * HWL + k0;

    float acc[10][4];
    #pragma unroll
    for (int t = 0; t < 10; ++t)
        #pragma unroll
        for (int j = 0; j < 4; ++j) acc[t][j] = 0.f;
    float psum[16];
    #pragma unroll
    for (int j = 0; j < 16; ++j) psum[j] = 0.f;

    for (int tI = 0; tI < tiles; ++tI) {
        __syncthreads();
        // load + split + store + rowsum partials (direct LDG; MLP-4 batches)
        #pragma unroll 4
        for (int j = 0; j < 16; ++j) {
            int row = lr + 4 * j;
            float4 v = *reinterpret_cast<const float4*>(base + (size_t)row * HWL + tI * 64 + lc * 4);
            psum[j] += (v.x + v.y) + (v.z + v.w);
            float4 h, l;
            h.x = hi_tf32(v.x); h.y = hi_tf32(v.y); h.z = hi_tf32(v.z); h.w = hi_tf32(v.w);
            l.x = v.x - h.x; l.y = v.y - h.y; l.z = v.z - h.z; l.w = v.w - h.w;
            *reinterpret_cast<float4*>(Xhi + row * RL + lc * 4) = h;
            *reinterpret_cast<float4*>(Xlo + row * RL + lc * 4) = l;
        }
        __syncthreads();

        if (wid == 0) cov_tile_mma<0, 0, 48, 6>(Xhi, Xlo, acc, r, c);
        else          cov_tile_mma<16, 2, 32, 4>(Xhi, Xlo, acc, r, c);
    }

    // rowsum reduction (reuse Xhi as [64][16] scratch)
    __syncthreads();
    #pragma unroll
    for (int j = 0; j < 16; ++j) Xhi[(lr + 4 * j) * 16 + lc] = psum[j];
    __syncthreads();
    const int p = n * 4 + q;
    {
        float s = 0.f;
        #pragma unroll
        for (int k = 0; k < 16; ++k) s += Xhi[tid * 16 + k];
        g_psum[g][p][tid] = s;
    }

    // write computed tiles
    float* outp = &g_pcov[g][p][0];
    const int M1 = wid ? 16 : 0,  M2 = wid ? 32 : 48;
    const int N1 = wid ? 2 : 0,   N2 = wid ? 4 : 6;
    const int T1 = 8 - N1;
    #pragma unroll
    for (int t2 = 0; t2 < 10; ++t2) {
        int strip = (t2 < T1) ? M1 : M2;
        int nt    = (t2 < T1) ? (t2 + N1) : (t2 - T1 + N2);
        int col   = nt * 8 + 2 * c;
        *reinterpret_cast<float2*>(outp + (size_t)(strip + r) * 64 + col)     = make_float2(acc[t2][0], acc[t2][1]);
        *reinterpret_cast<float2*>(outp + (size_t)(strip + r + 8) * 64 + col) = make_float2(acc[t2][2], acc[t2][3]);
    }
}

// =============================================================================
// Kernel 2a: reduce channel sums -> mu.  grid 8, 64 threads.
// =============================================================================
__global__ __launch_bounds__(64) void k_mean() {
    const int g = blockIdx.x, i = threadIdx.x;
    float s = 0.f;
    #pragma unroll 4
    for (int p = 0; p < NPART; ++p) s += g_psum[g][p][i];
    g_mu[g * LL + i] = s / (float)MTOT;
}

// =============================================================================
// Kernel 2b: reduce partial Grams -> cov, octet-upper only; mirror to lower.
// =============================================================================
__global__ __launch_bounds__(256) void k_cov_finalize() {
    const int g = blockIdx.y;
    const int e = blockIdx.x * 256 + threadIdx.x;
    const int i = e >> 6, j = e & 63;
    if ((j >> 3) < (i >> 3)) return;          // lower octet: filled by mirror
    float s0 = 0.f, s1 = 0.f, s2 = 0.f, s3 = 0.f;
    #pragma unroll 4
    for (int p = 0; p < NPART; p += 4) {
        s0 += g_pcov[g][p + 0][e];
        s1 += g_pcov[g][p + 1][e];
        s2 += g_pcov[g][p + 2][e];
        s3 += g_pcov[g][p + 3][e];
    }
    float c = ((s0 + s1) + (s2 + s3)) / (float)MTOT - g_mu[g * LL + i] * g_mu[g * LL + j];
    if (i == j) c += EPSV;
    g_cov[g * LL * LL + e] = c;
    if ((j >> 3) > (i >> 3)) g_cov[g * LL * LL + j * 64 + i] = c;
}

// =============================================================================
// Kernel 3: power iteration + deflation (unchanged — matched reference in R1).
// =============================================================================
#define MATVEC64(res, Aarr, vptr) {                                        \
    float y0 = 0.f, y1 = 0.f, y2 = 0.f, y3 = 0.f;                          \
    _Pragma("unroll")                                                      \
    for (int j_ = 0; j_ < 64; j_ += 4) {                                   \
        y0 = fmaf(Aarr[j_ + 0], (vptr)[j_ + 0], y0);                       \
        y1 = fmaf(Aarr[j_ + 1], (vptr)[j_ + 1], y1);                       \
        y2 = fmaf(Aarr[j_ + 2], (vptr)[j_ + 2], y2);                       \
        y3 = fmaf(Aarr[j_ + 3], (vptr)[j_ + 3], y3);                       \
    }                                                                      \
    res = (y0 + y1) + (y2 + y3);                                           \
}

__device__ __forceinline__ float sumsq64(const float* v) {
    float y0 = 0.f, y1 = 0.f, y2 = 0.f, y3 = 0.f;
    #pragma unroll
    for (int j = 0; j < 64; j += 4) {
        y0 = fmaf(v[j + 0], v[j + 0], y0);
        y1 = fmaf(v[j + 1], v[j + 1], y1);
        y2 = fmaf(v[j + 2], v[j + 2], y2);
        y3 = fmaf(v[j + 3], v[j + 3], y3);
    }
    return (y0 + y1) + (y2 + y3);
}
__device__ __forceinline__ float dot64(const float* a, const float* b) {
    float y0 = 0.f, y1 = 0.f, y2 = 0.f, y3 = 0.f;
    #pragma unroll
    for (int j = 0; j < 64; j += 4) {
        y0 = fmaf(a[j + 0], b[j + 0], y0);
        y1 = fmaf(a[j + 1], b[j + 1], y1);
        y2 = fmaf(a[j + 2], b[j + 2], y2);
        y3 = fmaf(a[j + 3], b[j + 3], y3);
    }
    return (y0 + y1) + (y2 + y3);
}

__global__ __launch_bounds__(64) void k_pi(const float* __restrict__ vinit) {
    const int g = blockIdx.x, i = threadIdx.x;
    __shared__ float vs[2][64];
    __shared__ float av[64];

    float A[64], S[64];
    #pragma unroll
    for (int j = 0; j < 64; ++j) {
        A[j] = g_cov[g * LL * LL + i * 64 + j];
        S[j] = 0.f;
    }

    float lam_prev = 0.f;

    for (int e = 0; e < 64; ++e) {
        __syncthreads();
        vs[0][i] = vinit[((size_t)g * LL + e) * LL + i];
        __syncthreads();

        float n2  = sumsq64(vs[0]);
        float inv = 1.f / (sqrtf(n2) + 1e-12f);
        int cur = 0;

        #pragma unroll 1
        for (int it = 0; it < 19; ++it) {
            float y;
            MATVEC64(y, A, vs[cur]);
            y *= inv;
            vs[cur ^ 1][i] = y;
            __syncthreads();
            cur ^= 1;
            n2  = sumsq64(vs[cur]);
            inv = 1.f / (sqrtf(n2) + 1e-12f);
        }

        float vi = vs[cur][i] * inv;
        __syncthreads();
        vs[cur ^ 1][i] = vi;
        __syncthreads();
        cur ^= 1;

        float Avi;
        MATVEC64(Avi, A, vs[cur]);
        av[i] = Avi;
        __syncthreads();

        float vAv = dot64(vs[cur], av);
        float vv  = sumsq64(vs[cur]);
        float lam = vAv / vv;

        if (e > 0 && (lam_prev < lam || lam < EPSV)) break;

        float svi = rsqrtf(lam) * vi;
        #pragma unroll
        for (int j = 0; j < 64; ++j) {
            float vj = vs[cur][j];
            S[j] = fmaf(svi, vj, S[j]);
            A[j] = fmaf(-Avi, vj, A[j]);
        }
        lam_prev = lam;
    }

    #pragma unroll
    for (int j = 0; j < 64; ++j) g_subT[g * LL * LL + j * 64 + i] = S[j];

    float t = 0.f;
    #pragma unroll
    for (int j = 0; j < 64; ++j) t = fmaf(S[j], g_mu[g * LL + j], t);
    g_t[g * LL + i] = t;
}

// =============================================================================
// Kernel 4: apply whitening + affine via 3xTF32 tensor MMA (R11 verbatim).
// out = (S @ x) * w + (b - t*w).  grid (7 hw-chunks, 32 n, 8 g), 128 threads.
// =============================================================================
#define AP_SMEM_BYTES ((2 * 64 * RL + 2 * 64 * RLX) * 4)

__global__ __launch_bounds__(128) void k_apply(const float* __restrict__ x,
                                               const float* __restrict__ wgt,
                                               const float* __restrict__ bia,
                                               float* __restrict__ out) {
    extern __shared__ __align__(16) float smem[];
    float* Shi = smem;
    float* Slo = smem + 64 * RL;
    float* Xh  = smem + 2 * 64 * RL;
    float* Xl  = Xh + 64 * RLX;

    const int hb = blockIdx.x;            // 0..6 (448 hw each)
    const int n  = blockIdx.y;
    const int g  = blockIdx.z;
    const int tid = threadIdx.x, wid = tid >> 5, lane = tid & 31;
    const int r = lane >> 2, c = lane & 3;
    const int mbase = wid * 16;
    const int lr = tid >> 4, lc = tid & 15;

    // load S transposed into [m][k] (hi/lo): g_subT[g][k*64+m] = S[m][k]
    const float* subT = g_subT + g * 4096;
    for (int idx = tid; idx < 1024; idx += 128) {
        int k = idx >> 4, m4 = idx & 15;
        float4 v = *reinterpret_cast<const float4*>(subT + k * 64 + m4 * 4);
        float h0 = hi_tf32(v.x), h1 = hi_tf32(v.y), h2 = hi_tf32(v.z), h3 = hi_tf32(v.w);
        Shi[(4 * m4 + 0) * RL + k] = h0;  Slo[(4 * m4 + 0) * RL + k] = v.x - h0;
        Shi[(4 * m4 + 1) * RL + k] = h1;  Slo[(4 * m4 + 1) * RL + k] = v.y - h1;
        Shi[(4 * m4 + 2) * RL + k] = h2;  Slo[(4 * m4 + 2) * RL + k] = v.z - h2;
        Shi[(4 * m4 + 3) * RL + k] = h3;  Slo[(4 * m4 + 3) * RL + k] = v.w - h3;
    }

    const float* xbase = x   + ((size_t)n * CC + (size_t)g * LL) * HWL + hb * 448;
    float*       obase = out + ((size_t)n * CC + (size_t)g * LL) * HWL + hb * 448;

    const int gc0 = g * LL + mbase + r, gc1 = gc0 + 8;
    const float w0 = wgt[gc0], w1 = wgt[gc1];
    const float q0 = bia[gc0] - g_t[gc0] * w0;
    const float q1 = bia[gc1] - g_t[gc1] * w1;

    float4 regs[8];
    #pragma unroll
    for (int j = 0; j < 8; ++j)
        regs[j] = *reinterpret_cast<const float4*>(xbase + (size_t)(lr + 8 * j) * HWL + lc * 4);

    for (int t = 0; t < 7; ++t) {
        __syncthreads();
        #pragma unroll
        for (int j = 0; j < 8; ++j) {
            float4 v = regs[j];
            float4 h, l;
            h.x = hi_tf32(v.x); h.y = hi_tf32(v.y); h.z = hi_tf32(v.z); h.w = hi_tf32(v.w);
            l.x = v.x - h.x; l.y = v.y - h.y; l.z = v.z - h.z; l.w = v.w - h.w;
            *reinterpret_cast<float4*>(Xh + (lr + 8 * j) * RLX + lc * 4) = h;
            *reinterpret_cast<float4*>(Xl + (lr + 8 * j) * RLX + lc * 4) = l;
        }
        __syncthreads();
        if (t < 6) {
            const float* b2 = xbase + (t + 1) * 64;
            #pragma unroll
            for (int j = 0; j < 8; ++j)
                regs[j] = *reinterpret_cast<const float4*>(b2 + (size_t)(lr + 8 * j) * HWL + lc * 4);
        }

        float acc[8][4];
        #pragma unroll
        for (int nt = 0; nt < 8; ++nt)
            #pragma unroll
            for (int j = 0; j < 4; ++j) acc[nt][j] = 0.f;

        #pragma unroll
        for (int ks = 0; ks < 8; ++ks) {
            const int ka = 8 * ks + c;
            uint32_t ah0 = fbits(Shi[(mbase + r) * RL + ka]);
            uint32_t ah1 = fbits(Shi[(mbase + r + 8) * RL + ka]);
            uint32_t ah2 = fbits(Shi[(mbase + r) * RL + ka + 4]);
            uint32_t ah3 = fbits(Shi[(mbase + r + 8) * RL + ka + 4]);
            uint32_t al0 = fbits(Slo[(mbase + r) * RL + ka]);
            uint32_t al1 = fbits(Slo[(mbase + r + 8) * RL + ka]);
            uint32_t al2 = fbits(Slo[(mbase + r) * RL + ka + 4]);
            uint32_t al3 = fbits(Slo[(mbase + r + 8) * RL + ka + 4]);
            #pragma unroll
            for (int nt = 0; nt < 8; ++nt) {
                const int bn = nt * 8 + r;
                uint32_t bh0 = fbits(Xh[ka * RLX + bn]);
                uint32_t bh1 = fbits(Xh[(ka + 4) * RLX + bn]);
                uint32_t bl0 = fbits(Xl[ka * RLX + bn]);
                uint32_t bl1 = fbits(Xl[(ka + 4) * RLX + bn]);
                mma_tf32(acc[nt], ah0, ah1, ah2, ah3, bh0, bh1);
                mma_tf32(acc[nt], ah0, ah1, ah2, ah3, bl0, bl1);
                mma_tf32(acc[nt], al0, al1, al2, al3, bh0, bh1);
            }
        }

        float* op = obase + t * 64;
        #pragma unroll
        for (int nt = 0; nt < 8; ++nt) {
            int col = nt * 8 + 2 * c;
            float2 v0 = make_float2(fmaf(acc[nt][0], w0, q0), fmaf(acc[nt][1], w0, q0));
            float2 v1 = make_float2(fmaf(acc[nt][2], w1, q1), fmaf(acc[nt][3], w1, q1));
            *reinterpret_cast<float2*>(op + (size_t)(mbase + r) * HWL + col)     = v0;
            *reinterpret_cast<float2*>(op + (size_t)(mbase + r + 8) * HWL + col) = v1;
        }
    }
}

// =============================================================================
extern "C" void kernel_launch(void* const* d_in, const int* in_sizes, int n_in,
                              void* d_out, int out_size) {
    const float* x     = (const float*)d_in[0];
    const float* vinit = (const float*)d_in[1];
    const float* wgt   = (const float*)d_in[2];
    const float* bia   = (const float*)d_in[3];
    float* out = (float*)d_out;
    (void)in_sizes; (void)n_in; (void)out_size;

    cudaFuncSetAttribute(k_apply, cudaFuncAttributeMaxDynamicSharedMemorySize, AP_SMEM_BYTES);

    k_cov_partial<<<dim3(4, 32, 8), 64>>>(x);
    k_mean<<<8, 64>>>();
    k_cov_finalize<<<dim3(16, 8), 256>>>();
    k_pi<<<8, 64>>>(vinit);
    k_apply<<<dim3(7, 32, 8), 128, AP_SMEM_BYTES>>>(x, wgt, bia, out);
}